// round 3
// baseline (speedup 1.0000x reference)
#include <cuda_runtime.h>

// VolumeRenderer: fused NeRF-style compositing.
// depth [R,128] f32 (sorted, in [2,6]), density [R,128] f32 (in [0,1)),
// feature [R,128,3] f32 -> out [R,4] f32 (r,g,b,depth)
// One warp per ray; each lane owns 4 consecutive samples (float4 loads).
//
// KEY FIX vs previous round: exclusive scan base is obtained via
// shfl_up(inclusive, 1) instead of (inclusive - own), because lane 31's own
// partial sum contains the 1e10 FAR_DELTA tau -> (x + 1e10) - 1e10 destroys
// all precision (ulp(1e10)=1024 in fp32) and corrupted the tail weights.

#define FULL 0xffffffffu

__global__ __launch_bounds__(256, 8)
void vr_kernel(const float4* __restrict__ inA,   // depth OR density
               const float4* __restrict__ inB,   // the other one
               const float4* __restrict__ feature,
               float4* __restrict__ out,
               int n_rays)
{
    // Disambiguate depth vs density by value range (depth >= 2, density < 1).
    const float probe = ((const float*)inA)[0];
    const float4* __restrict__ depth   = (probe >= 2.0f) ? inA : inB;
    const float4* __restrict__ density = (probe >= 2.0f) ? inB : inA;

    const int warp = (blockIdx.x * blockDim.x + threadIdx.x) >> 5;
    const int lane = threadIdx.x & 31;
    if (warp >= n_rays) return;

    const size_t row32 = (size_t)warp * 32;   // 128 floats = 32 float4
    const size_t row96 = (size_t)warp * 96;   // 384 floats = 96 float4

    // Lane owns samples p = 4*lane .. 4*lane+3
    float4 dep = depth[row32 + lane];
    float4 den = density[row32 + lane];
    const float4* frow = feature + row96 + lane * 3;
    float4 f0 = frow[0];  // {p0.r, p0.g, p0.b, p1.r}
    float4 f1 = frow[1];  // {p1.g, p1.b, p2.r, p2.g}
    float4 f2 = frow[2];  // {p2.b, p3.r, p3.g, p3.b}

    // deltas: depth[j+1]-depth[j]; last sample of the ray gets 1e10
    float nxt = __shfl_down_sync(FULL, dep.x, 1);
    float t0 = den.x * (dep.y - dep.x);
    float t1 = den.y * (dep.z - dep.y);
    float t2 = den.z * (dep.w - dep.z);
    float t3 = den.w * ((lane == 31) ? 1e10f : (nxt - dep.w));

    // per-lane inclusive prefix of tau
    float s0 = t0;
    float s1 = s0 + t1;
    float s2 = s1 + t2;
    float s3 = s2 + t3;   // lane 31: contains the 1e10 sentinel — fine, see below

    // warp inclusive scan of per-lane totals
    float v = s3;
    #pragma unroll
    for (int off = 1; off < 32; off <<= 1) {
        float n = __shfl_up_sync(FULL, v, off);
        if (lane >= off) v += n;
    }
    // exclusive base = previous lane's inclusive value (NO subtraction -> no
    // cancellation against the 1e10 term at lane 31)
    float base = __shfl_up_sync(FULL, v, 1);
    if (lane == 0) base = 0.0f;

    // w_j = exp(-excl_j) - exp(-incl_j)
    float e_prev = __expf(-base);
    float e0 = __expf(-(base + s0));
    float e1 = __expf(-(base + s1));
    float e2 = __expf(-(base + s2));
    float e3 = __expf(-(base + s3));   // lane31: underflows to 0 (or == e2 if den.w==0)
    float w0 = e_prev - e0;
    float w1 = e0 - e1;
    float w2 = e1 - e2;
    float w3 = e2 - e3;

    float r = w0 * f0.x + w1 * f0.w + w2 * f1.z + w3 * f2.y;
    float g = w0 * f0.y + w1 * f1.x + w2 * f1.w + w3 * f2.z;
    float b = w0 * f0.z + w1 * f1.y + w2 * f2.x + w3 * f2.w;
    float d = w0 * dep.x + w1 * dep.y + w2 * dep.z + w3 * dep.w;

    #pragma unroll
    for (int off = 16; off > 0; off >>= 1) {
        r += __shfl_down_sync(FULL, r, off);
        g += __shfl_down_sync(FULL, g, off);
        b += __shfl_down_sync(FULL, b, off);
        d += __shfl_down_sync(FULL, d, off);
    }

    if (lane == 0) out[warp] = make_float4(r, g, b, d);
}

extern "C" void kernel_launch(void* const* d_in, const int* in_sizes, int n_in,
                              void* d_out, int out_size)
{
    // feature = the (unique) largest input; remaining two disambiguated
    // in-kernel by value range.
    int fi = 2;
    for (int i = 0; i < 3; ++i)
        if (in_sizes[i] > in_sizes[(i + 1) % 3] && in_sizes[i] > in_sizes[(i + 2) % 3]) fi = i;
    int a = (fi == 0) ? 1 : 0;
    int b = (fi == 2) ? 1 : 2;
    if (b == fi || b == a) b = 3 - a - fi;

    const float4* inA     = (const float4*)d_in[a];
    const float4* inB     = (const float4*)d_in[b];
    const float4* feature = (const float4*)d_in[fi];
    float4* out = (float4*)d_out;

    int n_rays = in_sizes[a] / 128;
    int blocks = (n_rays + 7) / 8;   // 8 warps (rays) per 256-thread block
    vr_kernel<<<blocks, 256>>>(inA, inB, feature, out, n_rays);
}